// round 6
// baseline (speedup 1.0000x reference)
#include <cuda_runtime.h>

// VectorNormSelection, round 6.
// One warp per block, thread-per-row selection.
//  Phase A: lanes own 4-vector chunks (3x LDG.128 each, fully-consumed lines),
//    4 norms/lane/iter -> STS.128 into norms-only smem (stride 68 floats,
//    conflict-free); each lane zeroes its own row's 4-float pad (sentinel).
//  Phase B (thread = row):
//    pass 1: exact 16th-largest t via 4x Batcher sort16 (FMNMX, value-only)
//      + bitonic-halving merges (proven exact since R4).
//    pass 2: BRANCH-FREE compaction of indices with norm >= t into u32
//      scratch: slot = cand ? min(pos,17) : dummy(18); unconditional STS;
//      pos += cand. Sentinel idx 64 (-> padded 0.0 norm) pre-written to
//      slots 16,17 covers count==16/17 cases.
//    rank: all-pairs stable rank over 18 entries, values re-read from norms
//      smem; scatter ranked indices back into scratch.
//  Phase C: warp-cooperative gather from global (rows L2-hot), coalesced STG.

#define RPB   32
#define NPAD  68           // norms row stride in floats (272B); [64..67] = 0 pad
#define ISTR  21           // idx scratch stride in u32 (odd -> conflict-free)
#define SCR   18           // ranked entries per row (16 + up to 2 threshold ties)

// comparator: a <- max, b <- min
__device__ __forceinline__ void ceMM(float& a, float& b) {
    float lo = fminf(a, b);
    float hi = fmaxf(a, b);
    a = hi; b = lo;
}

// Batcher odd-even mergesort, n=16, descending, value-only (63 comparators)
__device__ __forceinline__ void sort16v(float (&v)[16]) {
#pragma unroll
    for (int p = 1; p < 16; p <<= 1) {
#pragma unroll
        for (int k = p; k >= 1; k >>= 1) {
#pragma unroll
            for (int j = k & (p - 1); j + k < 16; j += 2 * k) {
#pragma unroll
                for (int i = 0; i < k; i++) {
                    if (i + j + k < 16) {
                        if (((i + j) / (2 * p)) == ((i + j + k) / (2 * p)))
                            ceMM(v[i + j], v[i + j + k]);
                    }
                }
            }
        }
    }
}

__device__ __forceinline__ void loadN(const float* __restrict__ nr, int g, float (&v)[16]) {
    const float4* p = reinterpret_cast<const float4*>(nr + g * 16);
#pragma unroll
    for (int k = 0; k < 4; k++) {
        float4 q = p[k];
        v[4 * k + 0] = q.x; v[4 * k + 1] = q.y; v[4 * k + 2] = q.z; v[4 * k + 3] = q.w;
    }
}

__global__ void __launch_bounds__(RPB)
vecnorm_topk_kernel(const float* __restrict__ x, float* __restrict__ out, int nrows)
{
    __shared__ float    nsm[RPB * NPAD];      // 8704B: 64 norms + 4 pad / row
    __shared__ unsigned isc[RPB * ISTR];      // 2688B: idx scratch (+dummy)

    const int lane    = threadIdx.x;          // 0..31
    const int rowBase = blockIdx.x * RPB;
    if (rowBase >= nrows) return;
    const int rowsHere = min(RPB, nrows - rowBase);

    // ---- Phase A: chunk loads + norms -> smem ----
    const float4* gx = reinterpret_cast<const float4*>(x);
    const int subrow = lane >> 4;             // 0 or 1
    const int chunk  = lane & 15;             // 0..15
#pragma unroll 4
    for (int i = 0; i < 16; i++) {
        int lrow = 2 * i + subrow;
        int grow = rowBase + lrow;
        if (grow < nrows) {
            int base = grow * 48 + chunk * 3;
            float4 a = gx[base + 0];
            float4 b = gx[base + 1];
            float4 d = gx[base + 2];
            float n0 = fmaf(a.x, a.x, fmaf(a.y, a.y, a.z * a.z));
            float n1 = fmaf(a.w, a.w, fmaf(b.x, b.x, b.y * b.y));
            float n2 = fmaf(b.z, b.z, fmaf(b.w, b.w, d.x * d.x));
            float n3 = fmaf(d.y, d.y, fmaf(d.z, d.z, d.w * d.w));
            *reinterpret_cast<float4*>(nsm + lrow * NPAD + chunk * 4) =
                make_float4(n0, n1, n2, n3);
        }
    }
    // zero own row's pad (sentinel target), pre-write sentinel indices
    *reinterpret_cast<float4*>(nsm + lane * NPAD + 64) = make_float4(0.f, 0.f, 0.f, 0.f);
    unsigned* myidx = isc + lane * ISTR;
    myidx[16] = 64u;                          // sentinel: norm 0.0, ranks last
    myidx[17] = 64u;
    __syncwarp();

    // ---- Phase B: per-thread exact top-16 selection ----
    if (lane < rowsHere) {
        const float* nr = nsm + lane * NPAD;

        // pass 1: exact threshold t = 16th largest
        float rv[16];
        loadN(nr, 0, rv);
        sort16v(rv);
#pragma unroll 1
        for (int g = 1; g < 3; g++) {
            float cv[16];
            loadN(nr, g, cv);
            sort16v(cv);
#pragma unroll
            for (int i = 0; i < 16; i++) rv[i] = fmaxf(rv[i], cv[15 - i]);
#pragma unroll
            for (int j = 8; j >= 1; j >>= 1) {
#pragma unroll
                for (int tt = 0; tt < 16; tt++)
                    if ((tt & j) == 0) ceMM(rv[tt], rv[tt | j]);
            }
        }
        float t;
        {
            float cv[16];
            loadN(nr, 3, cv);
            sort16v(cv);
#pragma unroll
            for (int i = 0; i < 16; i++) rv[i] = fmaxf(rv[i], cv[15 - i]);
            float m0 = fminf(fminf(fminf(rv[0],  rv[1]),  fminf(rv[2],  rv[3])),
                             fminf(fminf(rv[4],  rv[5]),  fminf(rv[6],  rv[7])));
            float m1 = fminf(fminf(fminf(rv[8],  rv[9]),  fminf(rv[10], rv[11])),
                             fminf(fminf(rv[12], rv[13]), fminf(rv[14], rv[15])));
            t = fminf(m0, m1);
        }

        // pass 2: branch-free compaction of candidate indices (scan order)
        int pos = 0;
#pragma unroll 1
        for (int g = 0; g < 4; g++) {
            float cv[16];
            loadN(nr, g, cv);
#pragma unroll
            for (int k = 0; k < 16; k++) {
                bool c   = (cv[k] >= t);
                int slot = c ? min(pos, 17) : 18;      // dummy slot absorbs non-cands
                myidx[slot] = (unsigned)(g * 16 + k);  // unconditional STS.32
                pos += c;
            }
        }

        // rank: all-pairs stable (value desc, scan-slot asc)
        float v[SCR]; unsigned ixr[SCR]; int rk[SCR];
#pragma unroll
        for (int e = 0; e < SCR; e++) {
            ixr[e] = myidx[e];
            v[e]   = nr[ixr[e]];              // sentinel 64 -> 0.0 pad
            rk[e]  = 0;
        }
#pragma unroll
        for (int e = 0; e < SCR - 1; e++) {
#pragma unroll
            for (int f = e + 1; f < SCR; f++) {
                bool q = v[f] > v[e];
                rk[e] += q;
                rk[f] += !q;                  // ties -> earlier scan slot first
            }
        }
#pragma unroll
        for (int e = 0; e < SCR; e++)
            if (rk[e] < 16) myidx[rk[e]] = ixr[e];
    }
    __syncwarp();

    // ---- Phase C: warp-cooperative gather from global (L2-hot rows) ----
    {
        const int j1 = lane / 3,  c1 = lane - 3 * j1;           // out float [lane]
        const int f2 = 32 + lane;
        const int j2 = f2 / 3,    c2 = f2 - 3 * j2;             // out float [32+lane]
#pragma unroll 2
        for (int r = 0; r < rowsHere; r++) {
            int ro = rowBase + r;
            const unsigned* ord = isc + r * ISTR;
            unsigned i1 = ord[j1];
            out[ro * 48 + lane] = x[ro * 192 + (int)i1 * 3 + c1];
            if (lane < 16) {
                unsigned i2 = ord[j2];
                out[ro * 48 + 32 + lane] = x[ro * 192 + (int)i2 * 3 + c2];
            }
        }
    }
}

extern "C" void kernel_launch(void* const* d_in, const int* in_sizes, int n_in,
                              void* d_out, int out_size)
{
    const float* x   = (const float*)d_in[0];
    float*       out = (float*)d_out;
    int nrows = in_sizes[0] / 192;
    int grid  = (nrows + RPB - 1) / RPB;
    vecnorm_topk_kernel<<<grid, RPB>>>(x, out, nrows);
}

// round 7
// speedup vs baseline: 1.1736x; 1.1736x over previous
#include <cuda_runtime.h>

// VectorNormSelection, round 7: warp-per-row, zero shared memory.
// Each lane owns vectors 2l, 2l+1 of its warp's row (3 coalesced LDG.64).
// Keys: exact u64 = (norm_bits << 32) | (63 - idx). Norms >= 0 so unsigned
// order == value order; low bits give lower-index-first ties EXACTLY (full
// 32-bit value preserved -> exact jax.lax.top_k semantics, no threshold or
// rank machinery needed).
// Selection: bitonic sort-16 of the four 8-lane groups (parallel in one
// instruction stream), then tree merge via bitonic halving:
//   m[i] = max(a[i], b[15-i])  ==  shfl_xor(key, 15 / 23) + slot flip + max
// followed by a 4-stage descending bitonic clean. Top-16 lands sorted in
// lanes 0-7 (2 keys/lane).
// Epilogue: indices packed to bytes, 2 broadcasts/lane, gather from L1-hot
// row, coalesced 48-float stores.

#define WPB 8          // warps per block
#define RPW 4          // rows per warp

typedef unsigned long long u64;

__device__ __forceinline__ u64 cexg(u64 e, u64 p, bool takeMax) {
    // keep p iff (p > e) matches the desired direction
    return ((p > e) == takeMax) ? p : e;
}

// shuffle stage, element distance j = 2*JH (partner lane = lane ^ JH, same slot)
template <int JH>
__device__ __forceinline__ void stage_x(u64& e0, u64& e1, bool descR, int lane) {
    bool takeMax = (((lane & JH) == 0) == descR);
    u64 p0 = __shfl_xor_sync(0xffffffffu, e0, JH);
    u64 p1 = __shfl_xor_sync(0xffffffffu, e1, JH);
    e0 = cexg(e0, p0, takeMax);
    e1 = cexg(e1, p1, takeMax);
}

// element distance 1: both elements in-lane
__device__ __forceinline__ void stage_l(u64& e0, u64& e1, bool descR) {
    bool gt = e0 > e1;
    u64 hi = gt ? e0 : e1;
    u64 lo = gt ? e1 : e0;
    e0 = descR ? hi : lo;
    e1 = descR ? lo : hi;
}

__global__ void __launch_bounds__(WPB * 32)
vecnorm_topk_kernel(const float* __restrict__ x, float* __restrict__ out, int nrows)
{
    const int lane = threadIdx.x & 31;
    const int wg   = blockIdx.x * WPB + (threadIdx.x >> 5);
    const int rowBase = wg * RPW;

    // per-lane output routing constants
    const int f2 = 32 + lane;
    const int j1 = lane / 3, c1 = lane - 3 * j1;   // out float [lane]   <- rank j1, comp c1
    const int j2 = f2 / 3,   c2 = f2 - 3 * j2;     // out float [32+ln]  <- rank j2, comp c2

#pragma unroll 1
    for (int i = 0; i < RPW; i++) {
        int row = rowBase + i;
        if (row >= nrows) break;

        // ---- load 6 floats (vectors 2*lane, 2*lane+1), coalesced ----
        const float* xr = x + (size_t)row * 192;
        const float2* xr2 = reinterpret_cast<const float2*>(xr);
        float2 a = xr2[3 * lane + 0];
        float2 b = xr2[3 * lane + 1];
        float2 c = xr2[3 * lane + 2];
        float n0 = fmaf(a.x, a.x, fmaf(a.y, a.y, b.x * b.x));
        float n1 = fmaf(b.y, b.y, fmaf(c.x, c.x, c.y * c.y));

        // ---- exact keys ----
        u64 e0 = ((u64)__float_as_uint(n0) << 32) | (unsigned)(63 - 2 * lane);
        u64 e1 = ((u64)__float_as_uint(n1) << 32) | (unsigned)(62 - 2 * lane);

        // ---- bitonic sort-16 (desc) within each 8-lane group, 4 groups in parallel ----
        // directions use the element index within its 16-element group
        bool d2 = ((lane & 1) == 0);   // k=2  region bit
        bool d4 = ((lane & 2) == 0);   // k=4
        bool d8 = ((lane & 4) == 0);   // k=8
        stage_l(e0, e1, d2);                           // k=2  j=1
        stage_x<1>(e0, e1, d4, lane);                  // k=4  j=2
        stage_l(e0, e1, d4);                           //      j=1
        stage_x<2>(e0, e1, d8, lane);                  // k=8  j=4
        stage_x<1>(e0, e1, d8, lane);                  //      j=2
        stage_l(e0, e1, d8);                           //      j=1
        stage_x<4>(e0, e1, true, lane);                // k=16 j=8 (final: all desc)
        stage_x<2>(e0, e1, true, lane);                //      j=4
        stage_x<1>(e0, e1, true, lane);                //      j=2
        stage_l(e0, e1, true);                         //      j=1

        // ---- merge A: (g0,g1)->lanes0-7 and (g2,g3)->lanes16-23, in parallel ----
        {   // halving: partner element 15-i of the sibling group = lane^15, slot flip
            u64 p0 = __shfl_xor_sync(0xffffffffu, e0, 15);
            u64 p1 = __shfl_xor_sync(0xffffffffu, e1, 15);
            e0 = (p1 > e0) ? p1 : e0;
            e1 = (p0 > e1) ? p0 : e1;
        }
        stage_x<4>(e0, e1, true, lane);                // clean j=8
        stage_x<2>(e0, e1, true, lane);                //       j=4
        stage_x<1>(e0, e1, true, lane);                //       j=2
        stage_l(e0, e1, true);                         //       j=1

        // ---- merge B: lanes0-7 vs lanes16-23 -> final top-16 in lanes 0-7 ----
        {   // partner lane = 23 - l = l ^ 23 (for l<8), slot flip
            u64 p0 = __shfl_xor_sync(0xffffffffu, e0, 23);
            u64 p1 = __shfl_xor_sync(0xffffffffu, e1, 23);
            e0 = (p1 > e0) ? p1 : e0;
            e1 = (p0 > e1) ? p0 : e1;
        }
        stage_x<4>(e0, e1, true, lane);
        stage_x<2>(e0, e1, true, lane);
        stage_x<1>(e0, e1, true, lane);
        stage_l(e0, e1, true);

        // ---- extract indices, broadcast, gather (L1-hot), coalesced store ----
        unsigned idx0 = 63u - (unsigned)(e0 & 63ull);
        unsigned idx1 = 63u - (unsigned)(e1 & 63ull);
        unsigned pk = idx0 | (idx1 << 8);              // rank 2l | rank 2l+1

        unsigned pkA = __shfl_sync(0xffffffffu, pk, j1 >> 1);
        unsigned iA  = (j1 & 1) ? ((pkA >> 8) & 0xffu) : (pkA & 0xffu);
        unsigned pkB = __shfl_sync(0xffffffffu, pk, j2 >> 1);
        unsigned iB  = (j2 & 1) ? ((pkB >> 8) & 0xffu) : (pkB & 0xffu);

        float* outr = out + (size_t)row * 48;
        outr[lane] = xr[(int)iA * 3 + c1];
        if (lane < 16)
            outr[32 + lane] = xr[(int)iB * 3 + c2];
    }
}

extern "C" void kernel_launch(void* const* d_in, const int* in_sizes, int n_in,
                              void* d_out, int out_size)
{
    const float* x   = (const float*)d_in[0];
    float*       out = (float*)d_out;
    int nrows = in_sizes[0] / 192;
    int rowsPerBlock = WPB * RPW;
    int grid = (nrows + rowsPerBlock - 1) / rowsPerBlock;
    vecnorm_topk_kernel<<<grid, WPB * 32>>>(x, out, nrows);
}